// round 16
// baseline (speedup 1.0000x reference)
#include <cuda_runtime.h>
#include <cuda_fp16.h>
#include <stdint.h>
#include <cstdint>
#include <math.h>

#define B_ 2
#define T_ 2048
#define DM 768
#define NH 12
#define NKV 4
#define DH 64
#define WIN 512
#define GLB 64
#define MROWS (B_*T_)          // 4096
#define K2 1536                // stacked-K (2x) for fp16 hi/lo trick
#define KW 768                 // weight K (single copy; loader wraps)

// ---------------- scratch ----------------
__device__ __half g_ax[(size_t)MROWS*K2];        // split activations [4096][hi768|lo768]
__device__ __half g_wt1[(size_t)1280*KW];        // fp16 transposed [wq|wk|wv]
__device__ __half g_wt2[(size_t)DM*KW];          // fp16 transposed wo
__device__ float  g_kr[(size_t)B_*NKV*T_*DH];    // fallback k out
__device__ float  g_vr[(size_t)B_*NKV*T_*DH];    // fallback v out
__device__ __half g_qsp[(size_t)B_*NH*T_*128];   // Q' [b,h,t][hi64|lo64], pre-scaled 1/8
__device__ __half g_ksp[(size_t)B_*NKV*T_*DH];   // K fp16 [b,kvh,t][64]
__device__ __half g_vt[(size_t)B_*NKV*DH*T_];    // V^T fp16 [b,kvh,d][t]
__device__ float2 g_ropet[T_*32];                // cos/sin table [t][m]

// ---------------- helpers ----------------
__device__ __forceinline__ void cp16(void* smem, const void* gmem) {
    uint32_t s = (uint32_t)__cvta_generic_to_shared(smem);
    asm volatile("cp.async.cg.shared.global [%0], [%1], 16;\n" :: "r"(s), "l"(gmem));
}
__device__ __forceinline__ void cp_commit() { asm volatile("cp.async.commit_group;\n"); }

__device__ __forceinline__ void ldmx4(uint32_t* r, const void* p) {
    uint32_t a = (uint32_t)__cvta_generic_to_shared(p);
    asm volatile("ldmatrix.sync.aligned.m8n8.x4.shared.b16 {%0,%1,%2,%3}, [%4];"
                 : "=r"(r[0]), "=r"(r[1]), "=r"(r[2]), "=r"(r[3]) : "r"(a));
}
__device__ __forceinline__ void mma16816(float* d, const uint32_t* a, uint32_t b0, uint32_t b1) {
    asm volatile("mma.sync.aligned.m16n8k16.row.col.f32.f16.f16.f32 "
                 "{%0,%1,%2,%3}, {%4,%5,%6,%7}, {%8,%9}, {%0,%1,%2,%3};"
                 : "+f"(d[0]), "+f"(d[1]), "+f"(d[2]), "+f"(d[3])
                 : "r"(a[0]), "r"(a[1]), "r"(a[2]), "r"(a[3]), "r"(b0), "r"(b1));
}
__device__ __forceinline__ uint32_t packh2(float a, float b) {
    __half2 h = __floats2half2_rn(a, b);
    return *reinterpret_cast<uint32_t*>(&h);
}

// ---------------- prep: act split (vectorized) + weight transposes + rope table ----------------
#define N_ACT  (MROWS*DM)         // 3145728
#define N_ACT4 (N_ACT/4)          // 786432
#define N_W1   (1280*DM)          // 983040
#define N_W2   (DM*DM)            // 589824
#define N_TAB  (T_*32)            // 65536
__global__ void prep_kernel(const float* __restrict__ x,
                            const float* __restrict__ wq, const float* __restrict__ wk,
                            const float* __restrict__ wv, const float* __restrict__ wo,
                            __half* __restrict__ ax, __half* __restrict__ wt1,
                            __half* __restrict__ wt2, float2* __restrict__ ropet) {
    int idx = blockIdx.x * blockDim.x + threadIdx.x;
    if (idx < N_ACT4) {
        int e0 = idx * 4;
        int r = e0 / DM, c = e0 % DM;
        float4 v = *reinterpret_cast<const float4*>(&x[e0]);
        uint32_t h01 = packh2(v.x, v.y), h23 = packh2(v.z, v.w);
        float l0 = v.x - __half2float(__float2half_rn(v.x));
        float l1 = v.y - __half2float(__float2half_rn(v.y));
        float l2 = v.z - __half2float(__float2half_rn(v.z));
        float l3 = v.w - __half2float(__float2half_rn(v.w));
        size_t base = (size_t)r * K2;
        *reinterpret_cast<uint2*>(&ax[base + c])      = make_uint2(h01, h23);
        *reinterpret_cast<uint2*>(&ax[base + c + KW]) = make_uint2(packh2(l0, l1), packh2(l2, l3));
    } else if (idx < N_ACT4 + N_W1) {
        int e = idx - N_ACT4;
        int n = e / DM, k = e % DM;
        float v;
        if (n < 768)       v = wq[(size_t)k * 768 + n];
        else if (n < 1024) v = wk[(size_t)k * 256 + (n - 768)];
        else               v = wv[(size_t)k * 256 + (n - 1024)];
        wt1[(size_t)n * KW + k] = __float2half_rn(v);
    } else if (idx < N_ACT4 + N_W1 + N_W2) {
        int e = idx - N_ACT4 - N_W1;
        int n = e / DM, k = e % DM;
        wt2[(size_t)n * KW + k] = __float2half_rn(wo[(size_t)k * DM + n]);
    } else if (idx < N_ACT4 + N_W1 + N_W2 + N_TAB) {
        int e = idx - N_ACT4 - N_W1 - N_W2;
        int t = e >> 5, m = e & 31;
        float inv = powf(10000.0f, -(float)m / 32.0f);
        float s, c; sincosf((float)t * inv, &s, &c);
        ropet[e] = make_float2(c, s);
    }
}

// ---------------- GEMM shared config ----------------
#define BK 64
#define SAP 72
#define KT2 (K2/BK)   // 24

// ---------------- gemm1: QKV projection, 64x128 CTA tile, 256 thr / 8 warps (16x64 each) ----
// grid (10, 64) = 640 CTAs; fused RoPE/split epilogue.
#define A1STG (64*SAP)
#define B1STG (128*SAP)
__global__ void __launch_bounds__(256, 3)
gemm_qkv_kernel(const __half* __restrict__ A, const __half* __restrict__ Bt,
                __half* __restrict__ qsp, __half* __restrict__ ksp,
                float* __restrict__ kout, float* __restrict__ vout,
                const float2* __restrict__ ropet) {
    extern __shared__ __align__(16) __half smem_g[];
    __half* As = smem_g;                 // [2][A1STG]
    __half* Bs = smem_g + 2 * A1STG;     // [2][B1STG]

    int tid = threadIdx.x;
    int warp = tid >> 5, lane = tid & 31;
    int wm = warp & 3, wn = warp >> 2;   // 4 M-slices x 16 rows, 2 N-slices x 64 cols
    int bm = blockIdx.y * 64, bn = blockIdx.x * 128;
    int g = lane >> 2, t2 = (lane & 3) * 2;

    float acc[8][4];
    #pragma unroll
    for (int j = 0; j < 8; j++)
        #pragma unroll
        for (int r = 0; r < 4; r++) acc[j][r] = 0.f;

    auto load_stage = [&](int st, int kt) {
        int koff = kt * BK;
        int bko = koff < KW ? koff : koff - KW;
        #pragma unroll
        for (int i = 0; i < 2; i++) {              // A: 64 rows x 8 units = 512
            int u = tid + i * 256;
            int row = u >> 3, c8 = u & 7;
            cp16(&As[st * A1STG + row * SAP + c8 * 8],
                 A + (size_t)(bm + row) * K2 + koff + c8 * 8);
        }
        #pragma unroll
        for (int i = 0; i < 4; i++) {              // B: 128 rows x 8 units = 1024
            int u = tid + i * 256;
            int row = u >> 3, c8 = u & 7;
            cp16(&Bs[st * B1STG + row * SAP + c8 * 8],
                 Bt + (size_t)(bn + row) * KW + bko + c8 * 8);
        }
        cp_commit();
    };

    load_stage(0, 0);
    load_stage(1, 1);

    for (int kt = 0; kt < KT2; kt++) {
        int s = kt & 1;
        if (kt == KT2 - 1) asm volatile("cp.async.wait_group 0;\n");
        else               asm volatile("cp.async.wait_group 1;\n");
        __syncthreads();

        #pragma unroll
        for (int ks = 0; ks < BK; ks += 16) {
            uint32_t a[4];
            {
                int tile = lane >> 3, rr = lane & 7;
                int mrow = wm * 16 + (tile & 1) * 8 + rr;
                int kcol = ks + (tile >> 1) * 8;
                ldmx4(a, &As[s * A1STG + mrow * SAP + kcol]);
            }
            #pragma unroll
            for (int nfp = 0; nfp < 4; nfp++) {
                uint32_t bb[4];
                int tile = lane >> 3, rr = lane & 7;
                int nrow = wn * 64 + nfp * 16 + (tile >> 1) * 8 + rr;
                int kcol = ks + (tile & 1) * 8;
                ldmx4(bb, &Bs[s * B1STG + nrow * SAP + kcol]);
                mma16816(acc[2*nfp],   a, bb[0], bb[1]);
                mma16816(acc[2*nfp+1], a, bb[2], bb[3]);
            }
        }
        __syncthreads();
        if (kt + 2 < KT2) load_stage(s, kt + 2);
    }

    int hc = (bn + wn * 64) >> 6;          // head chunk 0..19 (warp-uniform)
    if (hc < 12) {                          // ---- Q: rope + scale + hi/lo split ----
        int h = hc;
        #pragma unroll
        for (int r2 = 0; r2 < 2; r2++) {
            int trow = bm + wm * 16 + g + r2 * 8;
            int b = trow >> 11, t = trow & (T_ - 1);
            size_t base = ((size_t)(b * NH + h) * T_ + t) * 128;
            #pragma unroll
            for (int nf = 0; nf < 4; nf++) {
                int m0 = nf * 8 + t2;
                float x0a = acc[nf][r2*2],     x0b = acc[nf][r2*2+1];
                float x1a = acc[nf+4][r2*2],   x1b = acc[nf+4][r2*2+1];
                float2 ca = ropet[t * 32 + m0];
                float2 cb = ropet[t * 32 + m0 + 1];
                float ra0 = (x0a*ca.x - x1a*ca.y) * 0.125f;
                float ra1 = (x1a*ca.x + x0a*ca.y) * 0.125f;
                float rb0 = (x0b*cb.x - x1b*cb.y) * 0.125f;
                float rb1 = (x1b*cb.x + x0b*cb.y) * 0.125f;
                *reinterpret_cast<uint32_t*>(&qsp[base + m0])      = packh2(ra0, rb0);
                *reinterpret_cast<uint32_t*>(&qsp[base + m0 + 32]) = packh2(ra1, rb1);
                float la0 = ra0 - __half2float(__float2half_rn(ra0));
                float lb0 = rb0 - __half2float(__float2half_rn(rb0));
                float la1 = ra1 - __half2float(__float2half_rn(ra1));
                float lb1 = rb1 - __half2float(__float2half_rn(rb1));
                *reinterpret_cast<uint32_t*>(&qsp[base + 64 + m0]) = packh2(la0, lb0);
                *reinterpret_cast<uint32_t*>(&qsp[base + 96 + m0]) = packh2(la1, lb1);
            }
        }
    } else if (hc < 16) {                   // ---- K: rope, fp32 out + fp16 ----
        int kvh = hc - 12;
        #pragma unroll
        for (int r2 = 0; r2 < 2; r2++) {
            int trow = bm + wm * 16 + g + r2 * 8;
            int b = trow >> 11, t = trow & (T_ - 1);
            size_t fb = ((size_t)(b * NKV + kvh) * T_ + t) * DH;
            #pragma unroll
            for (int nf = 0; nf < 4; nf++) {
                int m0 = nf * 8 + t2;
                float x0a = acc[nf][r2*2],     x0b = acc[nf][r2*2+1];
                float x1a = acc[nf+4][r2*2],   x1b = acc[nf+4][r2*2+1];
                float2 ca = ropet[t * 32 + m0];
                float2 cb = ropet[t * 32 + m0 + 1];
                float ra0 = x0a*ca.x - x1a*ca.y;
                float ra1 = x1a*ca.x + x0a*ca.y;
                float rb0 = x0b*cb.x - x1b*cb.y;
                float rb1 = x1b*cb.x + x0b*cb.y;
                *reinterpret_cast<float2*>(&kout[fb + m0])      = make_float2(ra0, rb0);
                *reinterpret_cast<float2*>(&kout[fb + m0 + 32]) = make_float2(ra1, rb1);
                *reinterpret_cast<uint32_t*>(&ksp[fb + m0])      = packh2(ra0, rb0);
                *reinterpret_cast<uint32_t*>(&ksp[fb + m0 + 32]) = packh2(ra1, rb1);
            }
        }
    } else {                                // ---- V: fp32 out + fp16 transposed ----
        int kvh = hc - 16;
        #pragma unroll
        for (int r2 = 0; r2 < 2; r2++) {
            int trow = bm + wm * 16 + g + r2 * 8;
            int b = trow >> 11, t = trow & (T_ - 1);
            size_t fb = ((size_t)(b * NKV + kvh) * T_ + t) * DH;
            size_t tb0 = (size_t)(b * NKV + kvh) * DH * T_ + t;
            #pragma unroll
            for (int nf = 0; nf < 8; nf++) {
                int d0 = nf * 8 + t2;
                float v0 = acc[nf][r2*2], v1 = acc[nf][r2*2+1];
                *reinterpret_cast<float2*>(&vout[fb + d0]) = make_float2(v0, v1);
                g_vt[tb0 + (size_t)d0 * T_]       = __float2half_rn(v0);
                g_vt[tb0 + (size_t)(d0 + 1) * T_] = __float2half_rn(v1);
            }
        }
    }
}

// ---------------- gemm2: 128x64 CTA tile, 256 thr / 8 warps (32x32 each) ----------------
// grid (12, 32) = 384 CTAs.
#define A2STG (128*SAP)
#define B2STG (64*SAP)
__global__ void __launch_bounds__(256, 3)
gemm_out_kernel(const __half* __restrict__ A, const __half* __restrict__ Bt,
                float* __restrict__ C, int N) {
    extern __shared__ __align__(16) __half smem_g[];
    __half* As = smem_g;                 // [2][A2STG]
    __half* Bs = smem_g + 2 * A2STG;     // [2][B2STG]

    int tid = threadIdx.x;
    int warp = tid >> 5, lane = tid & 31;
    int wm = warp & 3, wn = warp >> 2;   // 4 M-slices x 32 rows, 2 N-slices x 32 cols
    int bm = blockIdx.y * 128, bn = blockIdx.x * 64;
    int g = lane >> 2, t2 = (lane & 3) * 2;

    float acc[2][4][4];
    #pragma unroll
    for (int i = 0; i < 2; i++)
        #pragma unroll
        for (int j = 0; j < 4; j++)
            #pragma unroll
            for (int r = 0; r < 4; r++) acc[i][j][r] = 0.f;

    auto load_stage = [&](int st, int kt) {
        int koff = kt * BK;
        int bko = koff < KW ? koff : koff - KW;
        #pragma unroll
        for (int i = 0; i < 4; i++) {              // A: 128 rows x 8 units = 1024
            int u = tid + i * 256;
            int row = u >> 3, c8 = u & 7;
            cp16(&As[st * A2STG + row * SAP + c8 * 8],
                 A + (size_t)(bm + row) * K2 + koff + c8 * 8);
        }
        #pragma unroll
        for (int i = 0; i < 2; i++) {              // B: 64 rows x 8 units = 512
            int u = tid + i * 256;
            int row = u >> 3, c8 = u & 7;
            cp16(&Bs[st * B2STG + row * SAP + c8 * 8],
                 Bt + (size_t)(bn + row) * KW + bko + c8 * 8);
        }
        cp_commit();
    };

    load_stage(0, 0);
    load_stage(1, 1);

    for (int kt = 0; kt < KT2; kt++) {
        int s = kt & 1;
        if (kt == KT2 - 1) asm volatile("cp.async.wait_group 0;\n");
        else               asm volatile("cp.async.wait_group 1;\n");
        __syncthreads();

        #pragma unroll
        for (int ks = 0; ks < BK; ks += 16) {
            uint32_t a[2][4];
            #pragma unroll
            for (int mf = 0; mf < 2; mf++) {
                int tile = lane >> 3, rr = lane & 7;
                int mrow = wm * 32 + mf * 16 + (tile & 1) * 8 + rr;
                int kcol = ks + (tile >> 1) * 8;
                ldmx4(a[mf], &As[s * A2STG + mrow * SAP + kcol]);
            }
            #pragma unroll
            for (int nfp = 0; nfp < 2; nfp++) {
                uint32_t bb[4];
                int tile = lane >> 3, rr = lane & 7;
                int nrow = wn * 32 + nfp * 16 + (tile >> 1) * 8 + rr;
                int kcol = ks + (tile & 1) * 8;
                ldmx4(bb, &Bs[s * B2STG + nrow * SAP + kcol]);
                #pragma unroll
                for (int mf = 0; mf < 2; mf++) {
                    mma16816(acc[mf][2*nfp],   a[mf], bb[0], bb[1]);
                    mma16816(acc[mf][2*nfp+1], a[mf], bb[2], bb[3]);
                }
            }
        }
        __syncthreads();
        if (kt + 2 < KT2) load_stage(s, kt + 2);
    }

    #pragma unroll
    for (int mf = 0; mf < 2; mf++) {
        int r0 = bm + wm * 32 + mf * 16 + g;
        #pragma unroll
        for (int nf = 0; nf < 4; nf++) {
            int c0 = bn + wn * 32 + nf * 8 + t2;
            *reinterpret_cast<float2*>(&C[(size_t)r0 * N + c0]) =
                make_float2(acc[mf][nf][0], acc[mf][nf][1]);
            *reinterpret_cast<float2*>(&C[(size_t)(r0 + 8) * N + c0]) =
                make_float2(acc[mf][nf][2], acc[mf][nf][3]);
        }
    }
}

// ---------------- fp16 tensor-core windowed flash attention (frozen) ----------------
#define QSTR 136
#define KSTR 72
#define VSTR 72
#define CH 64

__global__ void __launch_bounds__(128, 4)
attn_mma_kernel(const __half* __restrict__ qsp,
                const __half* __restrict__ ksp,
                const __half* __restrict__ vt,
                __half* __restrict__ ax) {
    extern __shared__ __align__(16) __half sm[];
    __half* Qs = sm;
    __half* Ks = Qs + 64 * QSTR;
    __half* Vs = Ks + 2 * 64 * KSTR;

    int blk = blockIdx.x;
    int qt = 31 - blk / (B_ * NH);
    int rest = blk % (B_ * NH);
    int h = rest % NH, b = rest / NH;
    int kvh = h / (NH / NKV);
    int qbase = qt * 64;

    int tid = threadIdx.x, w = tid >> 5, lane = tid & 31;
    int g = lane >> 2, t2 = (lane & 3) * 2;

    const __half* Qg = qsp + ((size_t)(b * NH + h) * T_ + qbase) * 128;
    const __half* Kg = ksp + (size_t)(b * NKV + kvh) * T_ * DH;
    const __half* Vg = vt + (size_t)(b * NKV + kvh) * DH * T_;

    int wlo_key = qbase - (WIN - 1);
    if (wlo_key < GLB) wlo_key = GLB;
    wlo_key &= ~(CH - 1);
    int nch = 1 + ((qbase + 64 - wlo_key) >> 6 > 0 ? (qbase + 64 - wlo_key) >> 6 : 0);

    #pragma unroll
    for (int i = 0; i < 8; i++) {
        int u = tid + i * 128;
        int r = u >> 4, c = u & 15;
        cp16(&Qs[r * QSTR + c * 8], Qg + (size_t)r * 128 + c * 8);
    }

    auto load_chunk = [&](int buf, int c0) {
        __half* Kb = Ks + buf * 64 * KSTR;
        __half* Vb = Vs + buf * 64 * VSTR;
        #pragma unroll
        for (int i = 0; i < 4; i++) {
            int u = tid + i * 128;
            int r = u >> 3, c = u & 7;
            cp16(&Kb[r * KSTR + c * 8], Kg + (size_t)(c0 + r) * DH + c * 8);
        }
        #pragma unroll
        for (int i = 0; i < 4; i++) {
            int u = tid + i * 128;
            int r = u >> 3, c = u & 7;
            cp16(&Vb[r * VSTR + c * 8], Vg + (size_t)r * T_ + c0 + c * 8);
        }
    };

    load_chunk(0, 0);
    cp_commit();

    float O[8][4];
    #pragma unroll
    for (int nf = 0; nf < 8; nf++)
        #pragma unroll
        for (int r = 0; r < 4; r++) O[nf][r] = 0.f;
    float mrow[2] = {-1e30f, -1e30f};
    float lrow[2] = {0.f, 0.f};
    int irow0 = qbase + w * 16 + g;
    int wminr = qbase + w * 16;
    int wmaxr = wminr + 15;

    for (int idx = 0; idx < nch; idx++) {
        int buf = idx & 1;
        int c0 = (idx == 0) ? 0 : wlo_key + (idx - 1) * CH;
        if (idx + 1 < nch) {
            int c0n = (idx == 0) ? wlo_key : c0 + CH;
            load_chunk(buf ^ 1, c0n);
            cp_commit();
            asm volatile("cp.async.wait_group 1;\n");
        } else {
            asm volatile("cp.async.wait_group 0;\n");
        }
        __syncthreads();

        const __half* Kb = Ks + buf * 64 * KSTR;
        const __half* Vb = Vs + buf * 64 * VSTR;

        float sc[8][4];
        #pragma unroll
        for (int nf = 0; nf < 8; nf++)
            #pragma unroll
            for (int r = 0; r < 4; r++) sc[nf][r] = 0.f;

        #pragma unroll
        for (int kb = 0; kb < 4; kb++) {
            uint32_t aA[4], aB[4];
            {
                int tile = lane >> 3, rr = lane & 7;
                int mrw = w * 16 + (tile & 1) * 8 + rr;
                ldmx4(aA, &Qs[mrw * QSTR + kb * 32 + (tile >> 1) * 8]);
                ldmx4(aB, &Qs[mrw * QSTR + kb * 32 + 16 + (tile >> 1) * 8]);
            }
            int kk = (kb & 1) * 32;
            #pragma unroll
            for (int nf = 0; nf < 8; nf++) {
                uint32_t bb[4];
                ldmx4(bb, &Kb[(nf * 8 + (lane & 7)) * KSTR + kk + (lane >> 3) * 8]);
                mma16816(sc[nf], aA, bb[0], bb[1]);
                mma16816(sc[nf], aB, bb[2], bb[3]);
            }
        }

        bool full = (c0 + CH - 1 <= wminr) &&
                    ((c0 >= wmaxr - WIN + 1) || (c0 + CH - 1 < GLB));
        float cmax[2] = {-1e30f, -1e30f};
        if (full) {
            #pragma unroll
            for (int nf = 0; nf < 8; nf++)
                #pragma unroll
                for (int r = 0; r < 4; r++)
                    cmax[r >> 1] = fmaxf(cmax[r >> 1], sc[nf][r]);
        } else {
            #pragma unroll
            for (int nf = 0; nf < 8; nf++)
                #pragma unroll
                for (int r = 0; r < 4; r++) {
                    int j = c0 + nf * 8 + t2 + (r & 1);
                    int i = irow0 + (r >> 1) * 8;
                    bool a = (j <= i) && ((j > i - WIN) || (j < GLB) || (i < GLB));
                    float s = a ? sc[nf][r] : -1e30f;
                    sc[nf][r] = s;
                    cmax[r >> 1] = fmaxf(cmax[r >> 1], s);
                }
        }
        #pragma unroll
        for (int r2 = 0; r2 < 2; r2++) {
            cmax[r2] = fmaxf(cmax[r2], __shfl_xor_sync(0xffffffffu, cmax[r2], 1));
            cmax[r2] = fmaxf(cmax[r2], __shfl_xor_sync(0xffffffffu, cmax[r2], 2));
        }
        float scl[2], rsum[2] = {0.f, 0.f};
        #pragma unroll
        for (int r2 = 0; r2 < 2; r2++) {
            float mn = fmaxf(mrow[r2], cmax[r2]);
            scl[r2] = __expf(mrow[r2] - mn);
            mrow[r2] = mn;
        }
        #pragma unroll
        for (int nf = 0; nf < 8; nf++)
            #pragma unroll
            for (int r = 0; r < 4; r++) {
                float s = sc[nf][r];
                float p = (s > -5e29f) ? __expf(s - mrow[r >> 1]) : 0.f;
                sc[nf][r] = p;
                rsum[r >> 1] += p;
            }
        #pragma unroll
        for (int r2 = 0; r2 < 2; r2++) {
            rsum[r2] += __shfl_xor_sync(0xffffffffu, rsum[r2], 1);
            rsum[r2] += __shfl_xor_sync(0xffffffffu, rsum[r2], 2);
            lrow[r2] = lrow[r2] * scl[r2] + rsum[r2];
        }
        #pragma unroll
        for (int nf = 0; nf < 8; nf++) {
            O[nf][0] *= scl[0]; O[nf][1] *= scl[0];
            O[nf][2] *= scl[1]; O[nf][3] *= scl[1];
        }

        uint32_t Ph[4][4], Pl[4][4];
        #pragma unroll
        for (int f = 0; f < 4; f++) {
            float p0 = sc[2*f][0],   p1 = sc[2*f][1],   p2 = sc[2*f][2],   p3 = sc[2*f][3];
            float q0 = sc[2*f+1][0], q1 = sc[2*f+1][1], q2 = sc[2*f+1][2], q3 = sc[2*f+1][3];
            Ph[f][0] = packh2(p0, p1); Ph[f][1] = packh2(p2, p3);
            Ph[f][2] = packh2(q0, q1); Ph[f][3] = packh2(q2, q3);
            Pl[f][0] = packh2(p0 - __half2float(__float2half_rn(p0)),
                              p1 - __half2float(__float2half_rn(p1)));
            Pl[f][1] = packh2(p2 - __half2float(__float2half_rn(p2)),
                              p3 - __half2float(__float2half_rn(p3)));
            Pl[f][2] = packh2(q0 - __half2float(__float2half_rn(q0)),
                              q1 - __half2float(__float2half_rn(q1)));
            Pl[f][3] = packh2(q2 - __half2float(__float2half_rn(q2)),
                              q3 - __half2float(__float2half_rn(q3)));
        }

        #pragma unroll
        for (int nf = 0; nf < 8; nf++) {
            uint32_t va[4], vb[4];
            const __half* vrow = &Vb[(nf * 8 + (lane & 7)) * VSTR + (lane >> 3) * 8];
            ldmx4(va, vrow);
            ldmx4(vb, vrow + 32);
            mma16816(O[nf], Ph[0], va[0], va[1]);
            mma16816(O[nf], Ph[1], va[2], va[3]);
            mma16816(O[nf], Ph[2], vb[0], vb[1]);
            mma16816(O[nf], Ph[3], vb[2], vb[3]);
            mma16816(O[nf], Pl[0], va[0], va[1]);
            mma16816(O[nf], Pl[1], va[2], va[3]);
            mma16816(O[nf], Pl[2], vb[0], vb[1]);
            mma16816(O[nf], Pl[3], vb[2], vb[3]);
        }
        __syncthreads();
    }

    float inv0 = 1.0f / lrow[0], inv1 = 1.0f / lrow[1];
    size_t r0g = (size_t)b * T_ + irow0;
    size_t r1g = r0g + 8;
    #pragma unroll
    for (int nf = 0; nf < 8; nf++) {
        int col = h * DH + nf * 8 + t2;
        float v00 = O[nf][0] * inv0, v01 = O[nf][1] * inv0;
        float v10 = O[nf][2] * inv1, v11 = O[nf][3] * inv1;
        __half h00 = __float2half_rn(v00), h01 = __float2half_rn(v01);
        __half h10 = __float2half_rn(v10), h11 = __float2half_rn(v11);
        *reinterpret_cast<uint32_t*>(&ax[r0g * K2 + col]) = packh2(v00, v01);
        *reinterpret_cast<uint32_t*>(&ax[r1g * K2 + col]) = packh2(v10, v11);
        *reinterpret_cast<uint32_t*>(&ax[r0g * K2 + KW + col]) =
            packh2(v00 - __half2float(h00), v01 - __half2float(h01));
        *reinterpret_cast<uint32_t*>(&ax[r1g * K2 + KW + col]) =
            packh2(v10 - __half2float(h10), v11 - __half2float(h11));
    }
}

extern "C" void kernel_launch(void* const* d_in, const int* in_sizes, int n_in,
                              void* d_out, int out_size) {
    const float* x  = (const float*)d_in[0];
    const float* wq = (const float*)d_in[1];
    const float* wk = (const float*)d_in[2];
    const float* wv = (const float*)d_in[3];
    const float* wo = (const float*)d_in[4];
    float* out = (float*)d_out;

    __half *ax, *wt1, *wt2, *qsp, *ksp, *vt;
    float *kr, *vr;
    float2* ropet;
    cudaGetSymbolAddress((void**)&ax,    g_ax);
    cudaGetSymbolAddress((void**)&wt1,   g_wt1);
    cudaGetSymbolAddress((void**)&wt2,   g_wt2);
    cudaGetSymbolAddress((void**)&kr,    g_kr);
    cudaGetSymbolAddress((void**)&vr,    g_vr);
    cudaGetSymbolAddress((void**)&qsp,   g_qsp);
    cudaGetSymbolAddress((void**)&ksp,   g_ksp);
    cudaGetSymbolAddress((void**)&vt,    g_vt);
    cudaGetSymbolAddress((void**)&ropet, g_ropet);

    const int out_elems = B_ * T_ * DM;
    const int kv_elems  = B_ * NKV * T_ * DH;
    float* kout = kr; float* vout = vr;
    if (out_size >= out_elems + 2 * kv_elems) {
        kout = out + out_elems;
        vout = out + out_elems + kv_elems;
    }

    const int gemm1_smem = (2 * A1STG + 2 * B1STG) * 2;                    // 55296 B
    const int gemm2_smem = (2 * A2STG + 2 * B2STG) * 2;                    // 55296 B
    cudaFuncSetAttribute(gemm_qkv_kernel, cudaFuncAttributeMaxDynamicSharedMemorySize, gemm1_smem);
    cudaFuncSetAttribute(gemm_out_kernel, cudaFuncAttributeMaxDynamicSharedMemorySize, gemm2_smem);
    const int attn_smem = (64 * QSTR + 2 * 64 * KSTR + 2 * 64 * VSTR) * 2; // 54272 B
    cudaFuncSetAttribute(attn_mma_kernel, cudaFuncAttributeMaxDynamicSharedMemorySize, attn_smem);

    const int prep_total = N_ACT4 + N_W1 + N_W2 + N_TAB;
    prep_kernel<<<(prep_total + 255)/256, 256>>>(x, wq, wk, wv, wo, ax, wt1, wt2, ropet);

    gemm_qkv_kernel<<<dim3(1280/128, MROWS/64), 256, gemm1_smem>>>(ax, wt1, qsp, ksp,
                                                                   kout, vout, ropet);
    attn_mma_kernel<<<B_ * NH * (T_/64), 128, attn_smem>>>(qsp, ksp, vt, ax);
    gemm_out_kernel<<<dim3(DM/64, MROWS/128), 256, gemm2_smem>>>(ax, wt2, out, DM);
}

// round 17
// speedup vs baseline: 1.0705x; 1.0705x over previous
#include <cuda_runtime.h>
#include <cuda_fp16.h>
#include <stdint.h>
#include <cstdint>
#include <math.h>

#define B_ 2
#define T_ 2048
#define DM 768
#define NH 12
#define NKV 4
#define DH 64
#define WIN 512
#define GLB 64
#define MROWS (B_*T_)          // 4096
#define K2 1536                // stacked-K (2x) for fp16 hi/lo trick
#define KW 768                 // weight K (single copy; loader wraps)
#define QSCALE 0.18033688011112042f   // 0.125 * log2(e): attention runs in exp2 domain

// ---------------- scratch ----------------
__device__ __half g_ax[(size_t)MROWS*K2];        // split activations [4096][hi768|lo768]
__device__ __half g_wt1[(size_t)1280*KW];        // fp16 transposed [wq|wk|wv]
__device__ __half g_wt2[(size_t)DM*KW];          // fp16 transposed wo
__device__ float  g_kr[(size_t)B_*NKV*T_*DH];    // fallback k out
__device__ float  g_vr[(size_t)B_*NKV*T_*DH];    // fallback v out
__device__ __half g_qsp[(size_t)B_*NH*T_*128];   // Q' [b,h,t][hi64|lo64], pre-scaled
__device__ __half g_ksp[(size_t)B_*NKV*T_*DH];   // K fp16 [b,kvh,t][64]
__device__ __half g_vt[(size_t)B_*NKV*DH*T_];    // V^T fp16 [b,kvh,d][t]
__device__ float2 g_ropet[T_*32];                // cos/sin table [t][m]

// ---------------- helpers ----------------
__device__ __forceinline__ void cp16(void* smem, const void* gmem) {
    uint32_t s = (uint32_t)__cvta_generic_to_shared(smem);
    asm volatile("cp.async.cg.shared.global [%0], [%1], 16;\n" :: "r"(s), "l"(gmem));
}
__device__ __forceinline__ void cp_commit() { asm volatile("cp.async.commit_group;\n"); }

__device__ __forceinline__ void ldmx4(uint32_t* r, const void* p) {
    uint32_t a = (uint32_t)__cvta_generic_to_shared(p);
    asm volatile("ldmatrix.sync.aligned.m8n8.x4.shared.b16 {%0,%1,%2,%3}, [%4];"
                 : "=r"(r[0]), "=r"(r[1]), "=r"(r[2]), "=r"(r[3]) : "r"(a));
}
__device__ __forceinline__ void mma16816(float* d, const uint32_t* a, uint32_t b0, uint32_t b1) {
    asm volatile("mma.sync.aligned.m16n8k16.row.col.f32.f16.f16.f32 "
                 "{%0,%1,%2,%3}, {%4,%5,%6,%7}, {%8,%9}, {%0,%1,%2,%3};"
                 : "+f"(d[0]), "+f"(d[1]), "+f"(d[2]), "+f"(d[3])
                 : "r"(a[0]), "r"(a[1]), "r"(a[2]), "r"(a[3]), "r"(b0), "r"(b1));
}
__device__ __forceinline__ uint32_t packh2(float a, float b) {
    __half2 h = __floats2half2_rn(a, b);
    return *reinterpret_cast<uint32_t*>(&h);
}

// ---------------- prep: act split (vectorized) + weight transposes + rope table ----------------
#define N_ACT  (MROWS*DM)         // 3145728
#define N_ACT4 (N_ACT/4)          // 786432
#define N_W1   (1280*DM)          // 983040
#define N_W2   (DM*DM)            // 589824
#define N_TAB  (T_*32)            // 65536
__global__ void prep_kernel(const float* __restrict__ x,
                            const float* __restrict__ wq, const float* __restrict__ wk,
                            const float* __restrict__ wv, const float* __restrict__ wo,
                            __half* __restrict__ ax, __half* __restrict__ wt1,
                            __half* __restrict__ wt2, float2* __restrict__ ropet) {
    int idx = blockIdx.x * blockDim.x + threadIdx.x;
    if (idx < N_ACT4) {
        int e0 = idx * 4;
        int r = e0 / DM, c = e0 % DM;
        float4 v = *reinterpret_cast<const float4*>(&x[e0]);
        uint32_t h01 = packh2(v.x, v.y), h23 = packh2(v.z, v.w);
        float l0 = v.x - __half2float(__float2half_rn(v.x));
        float l1 = v.y - __half2float(__float2half_rn(v.y));
        float l2 = v.z - __half2float(__float2half_rn(v.z));
        float l3 = v.w - __half2float(__float2half_rn(v.w));
        size_t base = (size_t)r * K2;
        *reinterpret_cast<uint2*>(&ax[base + c])      = make_uint2(h01, h23);
        *reinterpret_cast<uint2*>(&ax[base + c + KW]) = make_uint2(packh2(l0, l1), packh2(l2, l3));
    } else if (idx < N_ACT4 + N_W1) {
        int e = idx - N_ACT4;
        int n = e / DM, k = e % DM;
        float v;
        if (n < 768)       v = wq[(size_t)k * 768 + n];
        else if (n < 1024) v = wk[(size_t)k * 256 + (n - 768)];
        else               v = wv[(size_t)k * 256 + (n - 1024)];
        wt1[(size_t)n * KW + k] = __float2half_rn(v);
    } else if (idx < N_ACT4 + N_W1 + N_W2) {
        int e = idx - N_ACT4 - N_W1;
        int n = e / DM, k = e % DM;
        wt2[(size_t)n * KW + k] = __float2half_rn(wo[(size_t)k * DM + n]);
    } else if (idx < N_ACT4 + N_W1 + N_W2 + N_TAB) {
        int e = idx - N_ACT4 - N_W1 - N_W2;
        int t = e >> 5, m = e & 31;
        float inv = powf(10000.0f, -(float)m / 32.0f);
        float s, c; sincosf((float)t * inv, &s, &c);
        ropet[e] = make_float2(c, s);
    }
}

// ---------------- GEMM shared config ----------------
#define BK 64
#define SAP 72
#define KT2 (K2/BK)   // 24

// ---------------- gemm1: QKV projection, 64x128 CTA tile, fused RoPE/split epilogue ----------------
// grid (1280/128=10, 4096/64=64) = 640 CTAs; 4 warps, warp tile 32x64.
#define A1STG (64*SAP)
#define B1STG (128*SAP)
__global__ void __launch_bounds__(128, 4)
gemm_qkv_kernel(const __half* __restrict__ A, const __half* __restrict__ Bt,
                __half* __restrict__ qsp, __half* __restrict__ ksp,
                float* __restrict__ kout, float* __restrict__ vout,
                const float2* __restrict__ ropet) {
    extern __shared__ __align__(16) __half smem_g[];
    __half* As = smem_g;                 // [2][A1STG]
    __half* Bs = smem_g + 2 * A1STG;     // [2][B1STG]

    int tid = threadIdx.x;
    int warp = tid >> 5, lane = tid & 31;
    int wm = warp & 1, wn = warp >> 1;   // wm: 32-row half, wn: 64-col half
    int bm = blockIdx.y * 64, bn = blockIdx.x * 128;
    int g = lane >> 2, t2 = (lane & 3) * 2;

    float acc[2][8][4];
    #pragma unroll
    for (int i = 0; i < 2; i++)
        #pragma unroll
        for (int j = 0; j < 8; j++)
            #pragma unroll
            for (int r = 0; r < 4; r++) acc[i][j][r] = 0.f;

    auto load_stage = [&](int st, int kt) {
        int koff = kt * BK;
        int bko = koff < KW ? koff : koff - KW;
        #pragma unroll
        for (int i = 0; i < 4; i++) {              // A: 64 rows x 8 units
            int u = tid + i * 128;
            int row = u >> 3, c8 = u & 7;
            cp16(&As[st * A1STG + row * SAP + c8 * 8],
                 A + (size_t)(bm + row) * K2 + koff + c8 * 8);
        }
        #pragma unroll
        for (int i = 0; i < 8; i++) {              // B: 128 rows x 8 units
            int u = tid + i * 128;
            int row = u >> 3, c8 = u & 7;
            cp16(&Bs[st * B1STG + row * SAP + c8 * 8],
                 Bt + (size_t)(bn + row) * KW + bko + c8 * 8);
        }
        cp_commit();
    };

    load_stage(0, 0);
    load_stage(1, 1);

    for (int kt = 0; kt < KT2; kt++) {
        int s = kt & 1;
        if (kt == KT2 - 1) asm volatile("cp.async.wait_group 0;\n");
        else               asm volatile("cp.async.wait_group 1;\n");
        __syncthreads();

        #pragma unroll
        for (int ks = 0; ks < BK; ks += 16) {
            uint32_t a[2][4];
            #pragma unroll
            for (int mf = 0; mf < 2; mf++) {
                int tile = lane >> 3, rr = lane & 7;
                int mrow = wm * 32 + mf * 16 + (tile & 1) * 8 + rr;
                int kcol = ks + (tile >> 1) * 8;
                ldmx4(a[mf], &As[s * A1STG + mrow * SAP + kcol]);
            }
            #pragma unroll
            for (int nfp = 0; nfp < 4; nfp++) {
                uint32_t bb[4];
                int tile = lane >> 3, rr = lane & 7;
                int nrow = wn * 64 + nfp * 16 + (tile >> 1) * 8 + rr;
                int kcol = ks + (tile & 1) * 8;
                ldmx4(bb, &Bs[s * B1STG + nrow * SAP + kcol]);
                #pragma unroll
                for (int mf = 0; mf < 2; mf++) {
                    mma16816(acc[mf][2*nfp],   a[mf], bb[0], bb[1]);
                    mma16816(acc[mf][2*nfp+1], a[mf], bb[2], bb[3]);
                }
            }
        }
        __syncthreads();
        if (kt + 2 < KT2) load_stage(s, kt + 2);
    }

    int hc = (bn + wn * 64) >> 6;          // head chunk 0..19 (warp-uniform)
    if (hc < 12) {                          // ---- Q: rope + exp2-domain scale + hi/lo split ----
        int h = hc;
        #pragma unroll
        for (int mf = 0; mf < 2; mf++)
            #pragma unroll
            for (int r2 = 0; r2 < 2; r2++) {
                int trow = bm + wm * 32 + mf * 16 + g + r2 * 8;
                int b = trow >> 11, t = trow & (T_ - 1);
                size_t base = ((size_t)(b * NH + h) * T_ + t) * 128;
                #pragma unroll
                for (int nf = 0; nf < 4; nf++) {
                    int m0 = nf * 8 + t2;
                    float x0a = acc[mf][nf][r2*2],     x0b = acc[mf][nf][r2*2+1];
                    float x1a = acc[mf][nf+4][r2*2],   x1b = acc[mf][nf+4][r2*2+1];
                    float2 ca = ropet[t * 32 + m0];
                    float2 cb = ropet[t * 32 + m0 + 1];
                    float ra0 = (x0a*ca.x - x1a*ca.y) * QSCALE;
                    float ra1 = (x1a*ca.x + x0a*ca.y) * QSCALE;
                    float rb0 = (x0b*cb.x - x1b*cb.y) * QSCALE;
                    float rb1 = (x1b*cb.x + x0b*cb.y) * QSCALE;
                    *reinterpret_cast<uint32_t*>(&qsp[base + m0])      = packh2(ra0, rb0);
                    *reinterpret_cast<uint32_t*>(&qsp[base + m0 + 32]) = packh2(ra1, rb1);
                    float la0 = ra0 - __half2float(__float2half_rn(ra0));
                    float lb0 = rb0 - __half2float(__float2half_rn(rb0));
                    float la1 = ra1 - __half2float(__float2half_rn(ra1));
                    float lb1 = rb1 - __half2float(__float2half_rn(rb1));
                    *reinterpret_cast<uint32_t*>(&qsp[base + 64 + m0]) = packh2(la0, lb0);
                    *reinterpret_cast<uint32_t*>(&qsp[base + 96 + m0]) = packh2(la1, lb1);
                }
            }
    } else if (hc < 16) {                   // ---- K: rope, fp32 out + fp16 ----
        int kvh = hc - 12;
        #pragma unroll
        for (int mf = 0; mf < 2; mf++)
            #pragma unroll
            for (int r2 = 0; r2 < 2; r2++) {
                int trow = bm + wm * 32 + mf * 16 + g + r2 * 8;
                int b = trow >> 11, t = trow & (T_ - 1);
                size_t fb = ((size_t)(b * NKV + kvh) * T_ + t) * DH;
                #pragma unroll
                for (int nf = 0; nf < 4; nf++) {
                    int m0 = nf * 8 + t2;
                    float x0a = acc[mf][nf][r2*2],     x0b = acc[mf][nf][r2*2+1];
                    float x1a = acc[mf][nf+4][r2*2],   x1b = acc[mf][nf+4][r2*2+1];
                    float2 ca = ropet[t * 32 + m0];
                    float2 cb = ropet[t * 32 + m0 + 1];
                    float ra0 = x0a*ca.x - x1a*ca.y;
                    float ra1 = x1a*ca.x + x0a*ca.y;
                    float rb0 = x0b*cb.x - x1b*cb.y;
                    float rb1 = x1b*cb.x + x0b*cb.y;
                    *reinterpret_cast<float2*>(&kout[fb + m0])      = make_float2(ra0, rb0);
                    *reinterpret_cast<float2*>(&kout[fb + m0 + 32]) = make_float2(ra1, rb1);
                    *reinterpret_cast<uint32_t*>(&ksp[fb + m0])      = packh2(ra0, rb0);
                    *reinterpret_cast<uint32_t*>(&ksp[fb + m0 + 32]) = packh2(ra1, rb1);
                }
            }
    } else {                                // ---- V: fp32 out + fp16 transposed ----
        int kvh = hc - 16;
        #pragma unroll
        for (int mf = 0; mf < 2; mf++)
            #pragma unroll
            for (int r2 = 0; r2 < 2; r2++) {
                int trow = bm + wm * 32 + mf * 16 + g + r2 * 8;
                int b = trow >> 11, t = trow & (T_ - 1);
                size_t fb = ((size_t)(b * NKV + kvh) * T_ + t) * DH;
                size_t tb0 = (size_t)(b * NKV + kvh) * DH * T_ + t;
                #pragma unroll
                for (int nf = 0; nf < 8; nf++) {
                    int d0 = nf * 8 + t2;
                    float v0 = acc[mf][nf][r2*2], v1 = acc[mf][nf][r2*2+1];
                    *reinterpret_cast<float2*>(&vout[fb + d0]) = make_float2(v0, v1);
                    g_vt[tb0 + (size_t)d0 * T_]       = __float2half_rn(v0);
                    g_vt[tb0 + (size_t)(d0 + 1) * T_] = __float2half_rn(v1);
                }
            }
    }
}

// ---------------- gemm2: 128x64 CTA tile, fp32-C output ----------------
// grid (768/64=12, 4096/128=32) = 384 CTAs; 4 warps, warp tile 64x32.
#define A2STG (128*SAP)
#define B2STG (64*SAP)
__global__ void __launch_bounds__(128, 4)
gemm_out_kernel(const __half* __restrict__ A, const __half* __restrict__ Bt,
                float* __restrict__ C, int N) {
    extern __shared__ __align__(16) __half smem_g[];
    __half* As = smem_g;                 // [2][A2STG]
    __half* Bs = smem_g + 2 * A2STG;     // [2][B2STG]

    int tid = threadIdx.x;
    int warp = tid >> 5, lane = tid & 31;
    int wm = warp & 1, wn = warp >> 1;   // wm: 64-row half, wn: 32-col half
    int bm = blockIdx.y * 128, bn = blockIdx.x * 64;
    int g = lane >> 2, t2 = (lane & 3) * 2;

    float acc[4][4][4];
    #pragma unroll
    for (int i = 0; i < 4; i++)
        #pragma unroll
        for (int j = 0; j < 4; j++)
            #pragma unroll
            for (int r = 0; r < 4; r++) acc[i][j][r] = 0.f;

    auto load_stage = [&](int st, int kt) {
        int koff = kt * BK;
        int bko = koff < KW ? koff : koff - KW;
        #pragma unroll
        for (int i = 0; i < 8; i++) {              // A: 128 rows x 8 units
            int u = tid + i * 128;
            int row = u >> 3, c8 = u & 7;
            cp16(&As[st * A2STG + row * SAP + c8 * 8],
                 A + (size_t)(bm + row) * K2 + koff + c8 * 8);
        }
        #pragma unroll
        for (int i = 0; i < 4; i++) {              // B: 64 rows x 8 units
            int u = tid + i * 128;
            int row = u >> 3, c8 = u & 7;
            cp16(&Bs[st * B2STG + row * SAP + c8 * 8],
                 Bt + (size_t)(bn + row) * KW + bko + c8 * 8);
        }
        cp_commit();
    };

    load_stage(0, 0);
    load_stage(1, 1);

    for (int kt = 0; kt < KT2; kt++) {
        int s = kt & 1;
        if (kt == KT2 - 1) asm volatile("cp.async.wait_group 0;\n");
        else               asm volatile("cp.async.wait_group 1;\n");
        __syncthreads();

        #pragma unroll
        for (int ks = 0; ks < BK; ks += 16) {
            uint32_t a[4][4];
            #pragma unroll
            for (int mf = 0; mf < 4; mf++) {
                int tile = lane >> 3, rr = lane & 7;
                int mrow = wm * 64 + mf * 16 + (tile & 1) * 8 + rr;
                int kcol = ks + (tile >> 1) * 8;
                ldmx4(a[mf], &As[s * A2STG + mrow * SAP + kcol]);
            }
            #pragma unroll
            for (int nfp = 0; nfp < 2; nfp++) {
                uint32_t bb[4];
                int tile = lane >> 3, rr = lane & 7;
                int nrow = wn * 32 + nfp * 16 + (tile >> 1) * 8 + rr;
                int kcol = ks + (tile & 1) * 8;
                ldmx4(bb, &Bs[s * B2STG + nrow * SAP + kcol]);
                #pragma unroll
                for (int mf = 0; mf < 4; mf++) {
                    mma16816(acc[mf][2*nfp],   a[mf], bb[0], bb[1]);
                    mma16816(acc[mf][2*nfp+1], a[mf], bb[2], bb[3]);
                }
            }
        }
        __syncthreads();
        if (kt + 2 < KT2) load_stage(s, kt + 2);
    }

    #pragma unroll
    for (int mf = 0; mf < 4; mf++) {
        int r0 = bm + wm * 64 + mf * 16 + g;
        #pragma unroll
        for (int nf = 0; nf < 4; nf++) {
            int c0 = bn + wn * 32 + nf * 8 + t2;
            *reinterpret_cast<float2*>(&C[(size_t)r0 * N + c0]) =
                make_float2(acc[mf][nf][0], acc[mf][nf][1]);
            *reinterpret_cast<float2*>(&C[(size_t)(r0 + 8) * N + c0]) =
                make_float2(acc[mf][nf][2], acc[mf][nf][3]);
        }
    }
}

// ---------------- fp16 tensor-core windowed flash attention (exp2 domain) ----------------
#define QSTR 136
#define KSTR 72
#define VSTR 72
#define CH 64

__global__ void __launch_bounds__(128, 4)
attn_mma_kernel(const __half* __restrict__ qsp,
                const __half* __restrict__ ksp,
                const __half* __restrict__ vt,
                __half* __restrict__ ax) {
    extern __shared__ __align__(16) __half sm[];
    __half* Qs = sm;
    __half* Ks = Qs + 64 * QSTR;
    __half* Vs = Ks + 2 * 64 * KSTR;

    int blk = blockIdx.x;
    int qt = 31 - blk / (B_ * NH);
    int rest = blk % (B_ * NH);
    int h = rest % NH, b = rest / NH;
    int kvh = h / (NH / NKV);
    int qbase = qt * 64;

    int tid = threadIdx.x, w = tid >> 5, lane = tid & 31;
    int g = lane >> 2, t2 = (lane & 3) * 2;

    const __half* Qg = qsp + ((size_t)(b * NH + h) * T_ + qbase) * 128;
    const __half* Kg = ksp + (size_t)(b * NKV + kvh) * T_ * DH;
    const __half* Vg = vt + (size_t)(b * NKV + kvh) * DH * T_;

    int wlo_key = qbase - (WIN - 1);
    if (wlo_key < GLB) wlo_key = GLB;
    wlo_key &= ~(CH - 1);
    int nch = 1 + ((qbase + 64 - wlo_key) >> 6 > 0 ? (qbase + 64 - wlo_key) >> 6 : 0);

    #pragma unroll
    for (int i = 0; i < 8; i++) {
        int u = tid + i * 128;
        int r = u >> 4, c = u & 15;
        cp16(&Qs[r * QSTR + c * 8], Qg + (size_t)r * 128 + c * 8);
    }

    auto load_chunk = [&](int buf, int c0) {
        __half* Kb = Ks + buf * 64 * KSTR;
        __half* Vb = Vs + buf * 64 * VSTR;
        #pragma unroll
        for (int i = 0; i < 4; i++) {
            int u = tid + i * 128;
            int r = u >> 3, c = u & 7;
            cp16(&Kb[r * KSTR + c * 8], Kg + (size_t)(c0 + r) * DH + c * 8);
        }
        #pragma unroll
        for (int i = 0; i < 4; i++) {
            int u = tid + i * 128;
            int r = u >> 3, c = u & 7;
            cp16(&Vb[r * VSTR + c * 8], Vg + (size_t)r * T_ + c0 + c * 8);
        }
    };

    load_chunk(0, 0);
    cp_commit();

    float O[8][4];
    #pragma unroll
    for (int nf = 0; nf < 8; nf++)
        #pragma unroll
        for (int r = 0; r < 4; r++) O[nf][r] = 0.f;
    float mrow[2] = {-1e30f, -1e30f};
    float lrow[2] = {0.f, 0.f};
    int irow0 = qbase + w * 16 + g;
    int wminr = qbase + w * 16;
    int wmaxr = wminr + 15;

    for (int idx = 0; idx < nch; idx++) {
        int buf = idx & 1;
        int c0 = (idx == 0) ? 0 : wlo_key + (idx - 1) * CH;
        if (idx + 1 < nch) {
            int c0n = (idx == 0) ? wlo_key : c0 + CH;
            load_chunk(buf ^ 1, c0n);
            cp_commit();
            asm volatile("cp.async.wait_group 1;\n");
        } else {
            asm volatile("cp.async.wait_group 0;\n");
        }
        __syncthreads();

        const __half* Kb = Ks + buf * 64 * KSTR;
        const __half* Vb = Vs + buf * 64 * VSTR;

        float sc[8][4];
        #pragma unroll
        for (int nf = 0; nf < 8; nf++)
            #pragma unroll
            for (int r = 0; r < 4; r++) sc[nf][r] = 0.f;

        #pragma unroll
        for (int kb = 0; kb < 4; kb++) {
            uint32_t aA[4], aB[4];
            {
                int tile = lane >> 3, rr = lane & 7;
                int mrw = w * 16 + (tile & 1) * 8 + rr;
                ldmx4(aA, &Qs[mrw * QSTR + kb * 32 + (tile >> 1) * 8]);
                ldmx4(aB, &Qs[mrw * QSTR + kb * 32 + 16 + (tile >> 1) * 8]);
            }
            int kk = (kb & 1) * 32;
            #pragma unroll
            for (int nf = 0; nf < 8; nf++) {
                uint32_t bb[4];
                ldmx4(bb, &Kb[(nf * 8 + (lane & 7)) * KSTR + kk + (lane >> 3) * 8]);
                mma16816(sc[nf], aA, bb[0], bb[1]);
                mma16816(sc[nf], aB, bb[2], bb[3]);
            }
        }

        bool full = (c0 + CH - 1 <= wminr) &&
                    ((c0 >= wmaxr - WIN + 1) || (c0 + CH - 1 < GLB));
        float cmax[2] = {-1e30f, -1e30f};
        if (full) {
            #pragma unroll
            for (int nf = 0; nf < 8; nf++)
                #pragma unroll
                for (int r = 0; r < 4; r++)
                    cmax[r >> 1] = fmaxf(cmax[r >> 1], sc[nf][r]);
        } else {
            #pragma unroll
            for (int nf = 0; nf < 8; nf++)
                #pragma unroll
                for (int r = 0; r < 4; r++) {
                    int j = c0 + nf * 8 + t2 + (r & 1);
                    int i = irow0 + (r >> 1) * 8;
                    bool a = (j <= i) && ((j > i - WIN) || (j < GLB) || (i < GLB));
                    float s = a ? sc[nf][r] : -1e30f;
                    sc[nf][r] = s;
                    cmax[r >> 1] = fmaxf(cmax[r >> 1], s);
                }
        }
        #pragma unroll
        for (int r2 = 0; r2 < 2; r2++) {
            cmax[r2] = fmaxf(cmax[r2], __shfl_xor_sync(0xffffffffu, cmax[r2], 1));
            cmax[r2] = fmaxf(cmax[r2], __shfl_xor_sync(0xffffffffu, cmax[r2], 2));
        }
        float scl[2], rsum[2] = {0.f, 0.f};
        #pragma unroll
        for (int r2 = 0; r2 < 2; r2++) {
            float mn = fmaxf(mrow[r2], cmax[r2]);
            scl[r2] = exp2f(mrow[r2] - mn);
            mrow[r2] = mn;
        }
        #pragma unroll
        for (int nf = 0; nf < 8; nf++)
            #pragma unroll
            for (int r = 0; r < 4; r++) {
                float s = sc[nf][r];
                float p = (s > -5e29f) ? exp2f(s - mrow[r >> 1]) : 0.f;
                sc[nf][r] = p;
                rsum[r >> 1] += p;
            }
        #pragma unroll
        for (int r2 = 0; r2 < 2; r2++) {
            rsum[r2] += __shfl_xor_sync(0xffffffffu, rsum[r2], 1);
            rsum[r2] += __shfl_xor_sync(0xffffffffu, rsum[r2], 2);
            lrow[r2] = lrow[r2] * scl[r2] + rsum[r2];
        }
        #pragma unroll
        for (int nf = 0; nf < 8; nf++) {
            O[nf][0] *= scl[0]; O[nf][1] *= scl[0];
            O[nf][2] *= scl[1]; O[nf][3] *= scl[1];
        }

        uint32_t Ph[4][4], Pl[4][4];
        #pragma unroll
        for (int f = 0; f < 4; f++) {
            float p0 = sc[2*f][0],   p1 = sc[2*f][1],   p2 = sc[2*f][2],   p3 = sc[2*f][3];
            float q0 = sc[2*f+1][0], q1 = sc[2*f+1][1], q2 = sc[2*f+1][2], q3 = sc[2*f+1][3];
            Ph[f][0] = packh2(p0, p1); Ph[f][1] = packh2(p2, p3);
            Ph[f][2] = packh2(q0, q1); Ph[f][3] = packh2(q2, q3);
            Pl[f][0] = packh2(p0 - __half2float(__float2half_rn(p0)),
                              p1 - __half2float(__float2half_rn(p1)));
            Pl[f][1] = packh2(p2 - __half2float(__float2half_rn(p2)),
                              p3 - __half2float(__float2half_rn(p3)));
            Pl[f][2] = packh2(q0 - __half2float(__float2half_rn(q0)),
                              q1 - __half2float(__float2half_rn(q1)));
            Pl[f][3] = packh2(q2 - __half2float(__float2half_rn(q2)),
                              q3 - __half2float(__float2half_rn(q3)));
        }

        #pragma unroll
        for (int nf = 0; nf < 8; nf++) {
            uint32_t va[4], vb[4];
            const __half* vrow = &Vb[(nf * 8 + (lane & 7)) * VSTR + (lane >> 3) * 8];
            ldmx4(va, vrow);
            ldmx4(vb, vrow + 32);
            mma16816(O[nf], Ph[0], va[0], va[1]);
            mma16816(O[nf], Ph[1], va[2], va[3]);
            mma16816(O[nf], Ph[2], vb[0], vb[1]);
            mma16816(O[nf], Ph[3], vb[2], vb[3]);
            mma16816(O[nf], Pl[0], va[0], va[1]);
            mma16816(O[nf], Pl[1], va[2], va[3]);
            mma16816(O[nf], Pl[2], vb[0], vb[1]);
            mma16816(O[nf], Pl[3], vb[2], vb[3]);
        }
        __syncthreads();
    }

    float inv0 = 1.0f / lrow[0], inv1 = 1.0f / lrow[1];
    size_t r0g = (size_t)b * T_ + irow0;
    size_t r1g = r0g + 8;
    #pragma unroll
    for (int nf = 0; nf < 8; nf++) {
        int col = h * DH + nf * 8 + t2;
        float v00 = O[nf][0] * inv0, v01 = O[nf][1] * inv0;
        float v10 = O[nf][2] * inv1, v11 = O[nf][3] * inv1;
        __half h00 = __float2half_rn(v00), h01 = __float2half_rn(v01);
        __half h10 = __float2half_rn(v10), h11 = __float2half_rn(v11);
        *reinterpret_cast<uint32_t*>(&ax[r0g * K2 + col]) = packh2(v00, v01);
        *reinterpret_cast<uint32_t*>(&ax[r1g * K2 + col]) = packh2(v10, v11);
        *reinterpret_cast<uint32_t*>(&ax[r0g * K2 + KW + col]) =
            packh2(v00 - __half2float(h00), v01 - __half2float(h01));
        *reinterpret_cast<uint32_t*>(&ax[r1g * K2 + KW + col]) =
            packh2(v10 - __half2float(h10), v11 - __half2float(h11));
    }
}

extern "C" void kernel_launch(void* const* d_in, const int* in_sizes, int n_in,
                              void* d_out, int out_size) {
    const float* x  = (const float*)d_in[0];
    const float* wq = (const float*)d_in[1];
    const float* wk = (const float*)d_in[2];
    const float* wv = (const float*)d_in[3];
    const float* wo = (const float*)d_in[4];
    float* out = (float*)d_out;

    __half *ax, *wt1, *wt2, *qsp, *ksp, *vt;
    float *kr, *vr;
    float2* ropet;
    cudaGetSymbolAddress((void**)&ax,    g_ax);
    cudaGetSymbolAddress((void**)&wt1,   g_wt1);
    cudaGetSymbolAddress((void**)&wt2,   g_wt2);
    cudaGetSymbolAddress((void**)&kr,    g_kr);
    cudaGetSymbolAddress((void**)&vr,    g_vr);
    cudaGetSymbolAddress((void**)&qsp,   g_qsp);
    cudaGetSymbolAddress((void**)&ksp,   g_ksp);
    cudaGetSymbolAddress((void**)&vt,    g_vt);
    cudaGetSymbolAddress((void**)&ropet, g_ropet);

    const int out_elems = B_ * T_ * DM;
    const int kv_elems  = B_ * NKV * T_ * DH;
    float* kout = kr; float* vout = vr;
    if (out_size >= out_elems + 2 * kv_elems) {
        kout = out + out_elems;
        vout = out + out_elems + kv_elems;
    }

    const int gemm1_smem = (2 * A1STG + 2 * B1STG) * 2;                    // 55296 B
    const int gemm2_smem = (2 * A2STG + 2 * B2STG) * 2;                    // 55296 B
    cudaFuncSetAttribute(gemm_qkv_kernel, cudaFuncAttributeMaxDynamicSharedMemorySize, gemm1_smem);
    cudaFuncSetAttribute(gemm_out_kernel, cudaFuncAttributeMaxDynamicSharedMemorySize, gemm2_smem);
    const int attn_smem = (64 * QSTR + 2 * 64 * KSTR + 2 * 64 * VSTR) * 2; // 54272 B
    cudaFuncSetAttribute(attn_mma_kernel, cudaFuncAttributeMaxDynamicSharedMemorySize, attn_smem);

    const int prep_total = N_ACT4 + N_W1 + N_W2 + N_TAB;
    prep_kernel<<<(prep_total + 255)/256, 256>>>(x, wq, wk, wv, wo, ax, wt1, wt2, ropet);

    gemm_qkv_kernel<<<dim3(1280/128, MROWS/64), 128, gemm1_smem>>>(ax, wt1, qsp, ksp,
                                                                   kout, vout, ropet);
    attn_mma_kernel<<<B_ * NH * (T_/64), 128, attn_smem>>>(qsp, ksp, vt, ax);
    gemm_out_kernel<<<dim3(DM/64, MROWS/128), 128, gemm2_smem>>>(ax, wt2, out, DM);
}